// round 5
// baseline (speedup 1.0000x reference)
#include <cuda_runtime.h>
#include <cstdint>

// Problem constants (fixed by the dataset)
#define NN     10000        // nodes
#define LD     13           // volume side
#define VOL    2197         // 13^3
#define VOLP   2208         // padded node stride (16B-aligned for float4 gathers)
#define KNB    8            // neighbors
#define PD     19           // padded side (13 + 2*3)

#define R0_SZ  5491         // ping buffer (19*17*17 max)
#define R1_SZ  6137         // pong buffer (19*19*17 max)

static __device__ float g_s1[(size_t)NN * VOLP];  // smoothed stage 1
static __device__ float g_s2[(size_t)NN * VOLP];  // smoothed stage 2

// Line-oriented separable 3-tap pooling pass, sliding window along tap axis.
// One div/mod per line, one load per input element, one store per output.
template<int NL, int BD, int IA, int IB, int OAs, int OBs,
         int LOOP, int ISTEP, int OSTEP, bool ISMAX>
__device__ __forceinline__ void pool_line(const float* __restrict__ in,
                                          float* __restrict__ out, float scale) {
    for (int line = threadIdx.x; line < NL; line += blockDim.x) {
        int b = line % BD;
        int a = line / BD;
        const float* p = in + a * IA + b * IB;
        float* q = out + a * OAs + b * OBs;
        float v0 = p[0];
        float v1 = p[ISTEP];
        #pragma unroll
        for (int t = 0; t < LOOP; ++t) {
            float v2 = p[(t + 2) * ISTEP];
            q[t * OSTEP] = ISMAX ? fmaxf(v0, fmaxf(v1, v2))
                                 : (v0 + v1 + v2) * scale;
            v0 = v1; v1 = v2;
        }
    }
    __syncthreads();
}

// Fused edge-pad + maxpool-z. Reads the 13^3 staging volume C; for each padded
// (x,y) line, loads the 13 clamped source values into registers once and emits
// the 17 sliding z-max outputs. Never materializes the 19^3 padded volume.
// Output layout: x*323 + y*17 + t  (19,19,17).
__device__ __forceinline__ void padmax_z(const float* __restrict__ C,
                                         float* __restrict__ out) {
    for (int line = threadIdx.x; line < PD * PD; line += blockDim.x) {
        int y = line % PD;
        int x = line / PD;
        int sx = min(max(x - 3, 0), LD - 1);
        int sy = min(max(y - 3, 0), LD - 1);
        const float* src = C + (sx * LD + sy) * LD;
        float s[LD];
        #pragma unroll
        for (int z = 0; z < LD; ++z) s[z] = src[z];
        float* q = out + x * 323 + y * 17;
        #pragma unroll
        for (int t = 0; t < 17; ++t) {
            // padded p[z] = s[clamp(z-3)], window {t, t+1, t+2}; clamps fold.
            const int c0 = (t - 3 < 0) ? 0 : ((t - 3 > 12) ? 12 : t - 3);
            const int c1 = (t - 2 < 0) ? 0 : ((t - 2 > 12) ? 12 : t - 2);
            const int c2 = (t - 1 < 0) ? 0 : ((t - 1 > 12) ? 12 : t - 1);
            q[t] = fmaxf(s[c0], fmaxf(s[c1], s[c2]));
        }
    }
    __syncthreads();
}

// Passes 2..9 of smooth (after padmax_z). Input (19,19,17) in R1.
// Pass 9 writes the final 13^3 directly to global gdst.
__device__ __forceinline__ void run_chain(float* R0, float* R1,
                                          float* __restrict__ gdst) {
    // max y: (19,19,17)->(19,17,17)
    pool_line<323, 17, 323,  1, 289,  1, 17,  17,  17, true >(R1, R0, 1.0f);
    // max x: ->(17,17,17)
    pool_line<289, 17,  17,  1,  17,  1, 17, 289, 289, true >(R0, R1, 1.0f);
    // avg z: ->(17,17,15)
    pool_line<289, 17, 289, 17, 255, 15, 15,   1,   1, false>(R1, R0, 1.0f);
    // avg y: ->(17,15,15)
    pool_line<255, 15, 255,  1, 225,  1, 15,  15,  15, false>(R0, R1, 1.0f);
    // avg x: ->(15,15,15)
    pool_line<225, 15,  15,  1,  15,  1, 15, 225, 225, false>(R1, R0, 1.0f / 27.0f);
    // avg z: ->(15,15,13)
    pool_line<225, 15, 225, 15, 195, 13, 13,   1,   1, false>(R0, R1, 1.0f);
    // avg y: ->(15,13,13)
    pool_line<195, 13, 195,  1, 169,  1, 13,  13,  13, false>(R1, R0, 1.0f);
    // avg x: ->(13,13,13)  -> GLOBAL
    pool_line<169, 13,  13,  1,  13,  1, 13, 169, 169, false>(R0, gdst, 1.0f / 27.0f);
}

// Kernel 1: s1[n] = smooth(alpha1 + alpha0 * cost[n])
__global__ void __launch_bounds__(256)
k_stage1(const float* __restrict__ cost, const float* __restrict__ alpha) {
    extern __shared__ float sm[];
    float* R0 = sm;            // R0_SZ floats (staging lives here first)
    float* R1 = sm + R0_SZ;    // R1_SZ floats
    int n = blockIdx.x;
    float a0 = alpha[0], a1 = alpha[1];
    const float* src = cost + (size_t)n * VOL;
    for (int v = threadIdx.x; v < VOL; v += blockDim.x)
        R0[v] = a1 + a0 * src[v];
    __syncthreads();
    padmax_z(R0, R1);
    run_chain(R0, R1, g_s1 + (size_t)n * VOLP);
}

#define GATH(c) (w0*f0.c + w1*f1.c + w2*f2.c + w3*f3.c + \
                 w4*f4.c + w5*f5.c + w6*f6.c + w7*f7.c)

// Kernel 2: gather s1 over knn -> combine with original cost -> smooth -> s2
__global__ void __launch_bounds__(256)
k_stage2(const float* __restrict__ cost, const int* __restrict__ knn,
         const float* __restrict__ dist, const float* __restrict__ alpha) {
    extern __shared__ float sm[];
    float* R0 = sm;
    float* R1 = sm + R0_SZ;
    __shared__ float ws[KNB];
    __shared__ int   nb[KNB];
    int n = blockIdx.x;
    if (threadIdx.x < KNB) {
        ws[threadIdx.x] = __expf(-dist[n * KNB + threadIdx.x] * 0.005f); // 1/(2*SIGMA^2)
        nb[threadIdx.x] = knn[n * KNB + threadIdx.x];
    }
    __syncthreads();
    float w0 = ws[0], w1 = ws[1], w2 = ws[2], w3 = ws[3];
    float w4 = ws[4], w5 = ws[5], w6 = ws[6], w7 = ws[7];
    float inv_norm = 1.0f / (w0 + w1 + w2 + w3 + w4 + w5 + w6 + w7);
    const float4* p0 = (const float4*)(g_s1 + (size_t)nb[0] * VOLP);
    const float4* p1 = (const float4*)(g_s1 + (size_t)nb[1] * VOLP);
    const float4* p2 = (const float4*)(g_s1 + (size_t)nb[2] * VOLP);
    const float4* p3 = (const float4*)(g_s1 + (size_t)nb[3] * VOLP);
    const float4* p4 = (const float4*)(g_s1 + (size_t)nb[4] * VOLP);
    const float4* p5 = (const float4*)(g_s1 + (size_t)nb[5] * VOLP);
    const float4* p6 = (const float4*)(g_s1 + (size_t)nb[6] * VOLP);
    const float4* p7 = (const float4*)(g_s1 + (size_t)nb[7] * VOLP);
    float a0 = alpha[0], a1 = alpha[1], a2 = alpha[2], a3 = alpha[3], a4 = alpha[4];
    // B = k2 + k1*cost + k3*gather
    float k1 = a2 * a0, k2 = a2 * a1 + a4, k3 = a3 * inv_norm;
    const float* src = cost + (size_t)n * VOL;
    float4* Bv = (float4*)R0;
    for (int v = threadIdx.x; v < VOL / 4; v += blockDim.x) {   // 549 float4s = 2196 floats
        float4 f0 = p0[v], f1 = p1[v], f2 = p2[v], f3 = p3[v];
        float4 f4 = p4[v], f5 = p5[v], f6 = p6[v], f7 = p7[v];
        const float* cs = src + 4 * v;
        float4 r;
        r.x = k2 + k1 * cs[0] + k3 * GATH(x);
        r.y = k2 + k1 * cs[1] + k3 * GATH(y);
        r.z = k2 + k1 * cs[2] + k3 * GATH(z);
        r.w = k2 + k1 * cs[3] + k3 * GATH(w);
        Bv[v] = r;
    }
    if (threadIdx.x == 0) {  // tail element 2196
        const int v = VOL - 1;
        const float* b = g_s1;
        float g = w0 * b[(size_t)nb[0] * VOLP + v] + w1 * b[(size_t)nb[1] * VOLP + v]
                + w2 * b[(size_t)nb[2] * VOLP + v] + w3 * b[(size_t)nb[3] * VOLP + v]
                + w4 * b[(size_t)nb[4] * VOLP + v] + w5 * b[(size_t)nb[5] * VOLP + v]
                + w6 * b[(size_t)nb[6] * VOLP + v] + w7 * b[(size_t)nb[7] * VOLP + v];
        R0[v] = k2 + k1 * src[v] + k3 * g;
    }
    __syncthreads();
    padmax_z(R0, R1);
    run_chain(R0, R1, g_s2 + (size_t)n * VOLP);
}

// Kernel 3: out[n] = alpha5 * (gather s2 over knn) / norm
__global__ void __launch_bounds__(256)
k_stage3(const int* __restrict__ knn, const float* __restrict__ dist,
         const float* __restrict__ alpha, float* __restrict__ out) {
    __shared__ float ws[KNB];
    __shared__ int   nb[KNB];
    int n = blockIdx.x;
    if (threadIdx.x < KNB) {
        ws[threadIdx.x] = __expf(-dist[n * KNB + threadIdx.x] * 0.005f);
        nb[threadIdx.x] = knn[n * KNB + threadIdx.x];
    }
    __syncthreads();
    float w0 = ws[0], w1 = ws[1], w2 = ws[2], w3 = ws[3];
    float w4 = ws[4], w5 = ws[5], w6 = ws[6], w7 = ws[7];
    float inv_norm = 1.0f / (w0 + w1 + w2 + w3 + w4 + w5 + w6 + w7);
    float s = alpha[5] * inv_norm;
    const float4* p0 = (const float4*)(g_s2 + (size_t)nb[0] * VOLP);
    const float4* p1 = (const float4*)(g_s2 + (size_t)nb[1] * VOLP);
    const float4* p2 = (const float4*)(g_s2 + (size_t)nb[2] * VOLP);
    const float4* p3 = (const float4*)(g_s2 + (size_t)nb[3] * VOLP);
    const float4* p4 = (const float4*)(g_s2 + (size_t)nb[4] * VOLP);
    const float4* p5 = (const float4*)(g_s2 + (size_t)nb[5] * VOLP);
    const float4* p6 = (const float4*)(g_s2 + (size_t)nb[6] * VOLP);
    const float4* p7 = (const float4*)(g_s2 + (size_t)nb[7] * VOLP);
    float* dst = out + (size_t)n * VOL;
    for (int v = threadIdx.x; v < VOL / 4; v += blockDim.x) {
        float4 f0 = p0[v], f1 = p1[v], f2 = p2[v], f3 = p3[v];
        float4 f4 = p4[v], f5 = p5[v], f6 = p6[v], f7 = p7[v];
        float* q = dst + 4 * v;
        q[0] = s * GATH(x);
        q[1] = s * GATH(y);
        q[2] = s * GATH(z);
        q[3] = s * GATH(w);
    }
    if (threadIdx.x == 0) {  // tail element 2196
        const int v = VOL - 1;
        const float* b = g_s2;
        float g = w0 * b[(size_t)nb[0] * VOLP + v] + w1 * b[(size_t)nb[1] * VOLP + v]
                + w2 * b[(size_t)nb[2] * VOLP + v] + w3 * b[(size_t)nb[3] * VOLP + v]
                + w4 * b[(size_t)nb[4] * VOLP + v] + w5 * b[(size_t)nb[5] * VOLP + v]
                + w6 * b[(size_t)nb[6] * VOLP + v] + w7 * b[(size_t)nb[7] * VOLP + v];
        dst[v] = s * g;
    }
}

extern "C" void kernel_launch(void* const* d_in, const int* in_sizes, int n_in,
                              void* d_out, int out_size) {
    const float* cost  = (const float*)d_in[0];
    const int*   knn   = (const int*)d_in[1];
    const float* dist  = (const float*)d_in[2];
    const float* alpha = (const float*)d_in[3];
    float* out = (float*)d_out;

    const int smem = (R0_SZ + R1_SZ) * (int)sizeof(float);  // 46512 B
    k_stage1<<<NN, 256, smem>>>(cost, alpha);
    k_stage2<<<NN, 256, smem>>>(cost, knn, dist, alpha);
    k_stage3<<<NN, 256>>>(knn, dist, alpha, out);
}

// round 6
// speedup vs baseline: 1.1085x; 1.1085x over previous
#include <cuda_runtime.h>
#include <cstdint>

// Problem constants (fixed by the dataset)
#define NN     10000        // nodes
#define LD     13           // volume side
#define VOL    2197         // 13^3
#define VOLP   2208         // padded node stride (16B-aligned for float4 gathers)
#define KNB    8            // neighbors
#define PD     19           // padded side (13 + 2*3)

#define BUF_SZ 6137         // single in-place work buffer: 19*19*17
#define C_SZ   2197         // staging volume
#define SMEMB  ((BUF_SZ + C_SZ) * 4)   // 33336 bytes

static __device__ float g_s1[(size_t)NN * VOLP];  // smoothed stage 1
static __device__ float g_s2[(size_t)NN * VOLP];  // smoothed stage 2

// ---------------------------------------------------------------------------
// In-place line passes over the fixed (323,17,1)-stride embedding.
// Forward sliding window: out[t] overwrites in[t] only after in[t..t+taps-1]
// are consumed into registers; lines are address-disjoint, so no cross-thread
// hazard. NOTE: single pointer, deliberately NOT __restrict__.
// ---------------------------------------------------------------------------

// 3-tap max, in-place.
template<int NL, int BD, int SA, int SB, int STEP, int LOOP>
__device__ __forceinline__ void max3_ip(float* buf) {
    for (int line = threadIdx.x; line < NL; line += blockDim.x) {
        int b = line % BD;
        int a = line / BD;
        float* p = buf + a * SA + b * SB;
        float v0 = p[0];
        float v1 = p[STEP];
        #pragma unroll
        for (int t = 0; t < LOOP; ++t) {
            float v2 = p[(t + 2) * STEP];
            p[t * STEP] = fmaxf(v0, fmaxf(v1, v2));
            v0 = v1; v1 = v2;
        }
    }
    __syncthreads();
}

// 5-tap fused avg-avg (weights 1,2,3,2,1 over 9), in-place.
template<int NL, int BD, int SA, int SB, int STEP, int LOOP>
__device__ __forceinline__ void avg5_ip(float* buf) {
    const float inv9 = 1.0f / 9.0f;
    for (int line = threadIdx.x; line < NL; line += blockDim.x) {
        int b = line % BD;
        int a = line / BD;
        float* p = buf + a * SA + b * SB;
        float v0 = p[0], v1 = p[STEP], v2 = p[2 * STEP], v3 = p[3 * STEP];
        #pragma unroll
        for (int t = 0; t < LOOP; ++t) {
            float v4 = p[(t + 4) * STEP];
            p[t * STEP] = ((v0 + v4) + 2.0f * (v1 + v3) + 3.0f * v2) * inv9;
            v0 = v1; v1 = v2; v2 = v3; v3 = v4;
        }
    }
    __syncthreads();
}

// Final 5-tap fused avg-avg along x, reading the embedding and writing the
// compact 13^3 result straight to global memory.
__device__ __forceinline__ void avg5_final(const float* __restrict__ buf,
                                           float* __restrict__ gdst) {
    const float inv9 = 1.0f / 9.0f;
    for (int line = threadIdx.x; line < 169; line += blockDim.x) {
        int u = line % 13;
        int v = line / 13;
        const float* p = buf + v * 17 + u;     // taps along x: stride 323
        float* q = gdst + v * 13 + u;          // out stride along x: 169
        float v0 = p[0], v1 = p[323], v2 = p[646], v3 = p[969];
        #pragma unroll
        for (int t = 0; t < 13; ++t) {
            float v4 = p[(t + 4) * 323];
            q[t * 169] = ((v0 + v4) + 2.0f * (v1 + v3) + 3.0f * v2) * inv9;
            v0 = v1; v1 = v2; v2 = v3; v3 = v4;
        }
    }
}

// Fused edge-pad + maxpool-z: reads 13^3 staging C, writes (19,19,17) into
// buf at strides (323,17,1). Clamps fold at compile time.
__device__ __forceinline__ void padmax_z(const float* __restrict__ C,
                                         float* __restrict__ buf) {
    for (int line = threadIdx.x; line < PD * PD; line += blockDim.x) {
        int y = line % PD;
        int x = line / PD;
        int sx = min(max(x - 3, 0), LD - 1);
        int sy = min(max(y - 3, 0), LD - 1);
        const float* src = C + (sx * LD + sy) * LD;
        float s[LD];
        #pragma unroll
        for (int z = 0; z < LD; ++z) s[z] = src[z];
        float* q = buf + x * 323 + y * 17;
        #pragma unroll
        for (int t = 0; t < 17; ++t) {
            const int c0 = (t - 3 < 0) ? 0 : ((t - 3 > 12) ? 12 : t - 3);
            const int c1 = (t - 2 < 0) ? 0 : ((t - 2 > 12) ? 12 : t - 2);
            const int c2 = (t - 1 < 0) ? 0 : ((t - 1 > 12) ? 12 : t - 1);
            q[t] = fmaxf(s[c0], fmaxf(s[c1], s[c2]));
        }
    }
    __syncthreads();
}

// Full smooth from staged 13^3 volume C to global gdst.
__device__ __forceinline__ void smooth(const float* C, float* buf,
                                       float* __restrict__ gdst) {
    padmax_z(C, buf);                                   // -> (19,19,17)
    max3_ip<323, 17, 323,  1,  17, 17>(buf);            // max y -> (19,17,17)
    max3_ip<289, 17,  17,  1, 323, 17>(buf);            // max x -> (17,17,17)
    avg5_ip<289, 17, 323, 17,   1, 13>(buf);            // avg2 z -> (17,17,13)
    avg5_ip<221, 13, 323,  1,  17, 13>(buf);            // avg2 y -> (17,13,13)
    avg5_final(buf, gdst);                              // avg2 x -> 13^3 global
}

// Kernel 1: s1[n] = smooth(alpha1 + alpha0 * cost[n])
__global__ void __launch_bounds__(384)
k_stage1(const float* __restrict__ cost, const float* __restrict__ alpha) {
    extern __shared__ float sm[];
    float* C   = sm;            // C_SZ floats
    float* buf = sm + C_SZ;     // BUF_SZ floats
    int n = blockIdx.x;
    float a0 = alpha[0], a1 = alpha[1];
    const float* src = cost + (size_t)n * VOL;
    for (int v = threadIdx.x; v < VOL; v += blockDim.x)
        C[v] = a1 + a0 * src[v];
    __syncthreads();
    smooth(C, buf, g_s1 + (size_t)n * VOLP);
}

#define GATH(c) (w0*f0.c + w1*f1.c + w2*f2.c + w3*f3.c + \
                 w4*f4.c + w5*f5.c + w6*f6.c + w7*f7.c)

// Kernel 2: gather s1 over knn -> combine with original cost -> smooth -> s2
__global__ void __launch_bounds__(384)
k_stage2(const float* __restrict__ cost, const int* __restrict__ knn,
         const float* __restrict__ dist, const float* __restrict__ alpha) {
    extern __shared__ float sm[];
    float* C   = sm;
    float* buf = sm + C_SZ;
    __shared__ float ws[KNB];
    __shared__ int   nb[KNB];
    int n = blockIdx.x;
    if (threadIdx.x < KNB) {
        ws[threadIdx.x] = __expf(-dist[n * KNB + threadIdx.x] * 0.005f); // 1/(2*SIGMA^2)
        nb[threadIdx.x] = knn[n * KNB + threadIdx.x];
    }
    __syncthreads();
    float w0 = ws[0], w1 = ws[1], w2 = ws[2], w3 = ws[3];
    float w4 = ws[4], w5 = ws[5], w6 = ws[6], w7 = ws[7];
    float inv_norm = 1.0f / (w0 + w1 + w2 + w3 + w4 + w5 + w6 + w7);
    const float4* p0 = (const float4*)(g_s1 + (size_t)nb[0] * VOLP);
    const float4* p1 = (const float4*)(g_s1 + (size_t)nb[1] * VOLP);
    const float4* p2 = (const float4*)(g_s1 + (size_t)nb[2] * VOLP);
    const float4* p3 = (const float4*)(g_s1 + (size_t)nb[3] * VOLP);
    const float4* p4 = (const float4*)(g_s1 + (size_t)nb[4] * VOLP);
    const float4* p5 = (const float4*)(g_s1 + (size_t)nb[5] * VOLP);
    const float4* p6 = (const float4*)(g_s1 + (size_t)nb[6] * VOLP);
    const float4* p7 = (const float4*)(g_s1 + (size_t)nb[7] * VOLP);
    float a0 = alpha[0], a1 = alpha[1], a2 = alpha[2], a3 = alpha[3], a4 = alpha[4];
    float k1 = a2 * a0, k2 = a2 * a1 + a4, k3 = a3 * inv_norm;
    const float* src = cost + (size_t)n * VOL;
    float4* Cv = (float4*)C;
    for (int v = threadIdx.x; v < VOL / 4; v += blockDim.x) {   // 549 float4s
        float4 f0 = p0[v], f1 = p1[v], f2 = p2[v], f3 = p3[v];
        float4 f4 = p4[v], f5 = p5[v], f6 = p6[v], f7 = p7[v];
        const float* cs = src + 4 * v;
        float4 r;
        r.x = k2 + k1 * cs[0] + k3 * GATH(x);
        r.y = k2 + k1 * cs[1] + k3 * GATH(y);
        r.z = k2 + k1 * cs[2] + k3 * GATH(z);
        r.w = k2 + k1 * cs[3] + k3 * GATH(w);
        Cv[v] = r;
    }
    if (threadIdx.x == 0) {  // tail element 2196
        const int v = VOL - 1;
        const float* b = g_s1;
        float g = w0 * b[(size_t)nb[0] * VOLP + v] + w1 * b[(size_t)nb[1] * VOLP + v]
                + w2 * b[(size_t)nb[2] * VOLP + v] + w3 * b[(size_t)nb[3] * VOLP + v]
                + w4 * b[(size_t)nb[4] * VOLP + v] + w5 * b[(size_t)nb[5] * VOLP + v]
                + w6 * b[(size_t)nb[6] * VOLP + v] + w7 * b[(size_t)nb[7] * VOLP + v];
        C[v] = k2 + k1 * src[v] + k3 * g;
    }
    __syncthreads();
    smooth(C, buf, g_s2 + (size_t)n * VOLP);
}

// Kernel 3: out[n] = alpha5 * (gather s2 over knn) / norm
__global__ void __launch_bounds__(256)
k_stage3(const int* __restrict__ knn, const float* __restrict__ dist,
         const float* __restrict__ alpha, float* __restrict__ out) {
    __shared__ float ws[KNB];
    __shared__ int   nb[KNB];
    int n = blockIdx.x;
    if (threadIdx.x < KNB) {
        ws[threadIdx.x] = __expf(-dist[n * KNB + threadIdx.x] * 0.005f);
        nb[threadIdx.x] = knn[n * KNB + threadIdx.x];
    }
    __syncthreads();
    float w0 = ws[0], w1 = ws[1], w2 = ws[2], w3 = ws[3];
    float w4 = ws[4], w5 = ws[5], w6 = ws[6], w7 = ws[7];
    float inv_norm = 1.0f / (w0 + w1 + w2 + w3 + w4 + w5 + w6 + w7);
    float s = alpha[5] * inv_norm;
    const float4* p0 = (const float4*)(g_s2 + (size_t)nb[0] * VOLP);
    const float4* p1 = (const float4*)(g_s2 + (size_t)nb[1] * VOLP);
    const float4* p2 = (const float4*)(g_s2 + (size_t)nb[2] * VOLP);
    const float4* p3 = (const float4*)(g_s2 + (size_t)nb[3] * VOLP);
    const float4* p4 = (const float4*)(g_s2 + (size_t)nb[4] * VOLP);
    const float4* p5 = (const float4*)(g_s2 + (size_t)nb[5] * VOLP);
    const float4* p6 = (const float4*)(g_s2 + (size_t)nb[6] * VOLP);
    const float4* p7 = (const float4*)(g_s2 + (size_t)nb[7] * VOLP);
    float* dst = out + (size_t)n * VOL;
    for (int v = threadIdx.x; v < VOL / 4; v += blockDim.x) {
        float4 f0 = p0[v], f1 = p1[v], f2 = p2[v], f3 = p3[v];
        float4 f4 = p4[v], f5 = p5[v], f6 = p6[v], f7 = p7[v];
        float* q = dst + 4 * v;
        q[0] = s * GATH(x);
        q[1] = s * GATH(y);
        q[2] = s * GATH(z);
        q[3] = s * GATH(w);
    }
    if (threadIdx.x == 0) {  // tail element 2196
        const int v = VOL - 1;
        const float* b = g_s2;
        float g = w0 * b[(size_t)nb[0] * VOLP + v] + w1 * b[(size_t)nb[1] * VOLP + v]
                + w2 * b[(size_t)nb[2] * VOLP + v] + w3 * b[(size_t)nb[3] * VOLP + v]
                + w4 * b[(size_t)nb[4] * VOLP + v] + w5 * b[(size_t)nb[5] * VOLP + v]
                + w6 * b[(size_t)nb[6] * VOLP + v] + w7 * b[(size_t)nb[7] * VOLP + v];
        dst[v] = s * g;
    }
}

extern "C" void kernel_launch(void* const* d_in, const int* in_sizes, int n_in,
                              void* d_out, int out_size) {
    const float* cost  = (const float*)d_in[0];
    const int*   knn   = (const int*)d_in[1];
    const float* dist  = (const float*)d_in[2];
    const float* alpha = (const float*)d_in[3];
    float* out = (float*)d_out;

    k_stage1<<<NN, 384, SMEMB>>>(cost, alpha);
    k_stage2<<<NN, 384, SMEMB>>>(cost, knn, dist, alpha);
    k_stage3<<<NN, 256>>>(knn, dist, alpha, out);
}

// round 7
// speedup vs baseline: 1.1502x; 1.0376x over previous
#include <cuda_runtime.h>
#include <cstdint>

// Problem constants (fixed by the dataset)
#define NN     10000        // nodes
#define LD     13           // volume side
#define VOL    2197         // 13^3
#define VOLP   2208         // padded node stride (16B-aligned for float4 gathers)
#define KNB    8            // neighbors
#define PD     19           // padded side (13 + 2*3)

#define BUF_SZ 6137         // single in-place work buffer: 19*19*17
#define C_SZ   2197         // staging volume
#define SMEMB  ((BUF_SZ + C_SZ) * 4)   // 33336 bytes

static __device__ float g_s1[(size_t)NN * VOLP];  // smoothed stage 1
static __device__ float g_s2[(size_t)NN * VOLP];  // smoothed stage 2

// ---------------------------------------------------------------------------
// In-place line passes over the fixed (323,17,1)-stride embedding.
// Forward sliding window: out[t] overwrites in[t] only after in[t..t+taps-1]
// are consumed into registers; lines are address-disjoint, so no cross-thread
// hazard. NOTE: single pointer, deliberately NOT __restrict__.
// ---------------------------------------------------------------------------

// 3-tap max, in-place.
template<int NL, int BD, int SA, int SB, int STEP, int LOOP>
__device__ __forceinline__ void max3_ip(float* buf) {
    for (int line = threadIdx.x; line < NL; line += blockDim.x) {
        int b = line % BD;
        int a = line / BD;
        float* p = buf + a * SA + b * SB;
        float v0 = p[0];
        float v1 = p[STEP];
        #pragma unroll
        for (int t = 0; t < LOOP; ++t) {
            float v2 = p[(t + 2) * STEP];
            p[t * STEP] = fmaxf(v0, fmaxf(v1, v2));
            v0 = v1; v1 = v2;
        }
    }
    __syncthreads();
}

// 5-tap fused avg-avg (weights 1,2,3,2,1 over 9), in-place.
template<int NL, int BD, int SA, int SB, int STEP, int LOOP>
__device__ __forceinline__ void avg5_ip(float* buf) {
    const float inv9 = 1.0f / 9.0f;
    for (int line = threadIdx.x; line < NL; line += blockDim.x) {
        int b = line % BD;
        int a = line / BD;
        float* p = buf + a * SA + b * SB;
        float v0 = p[0], v1 = p[STEP], v2 = p[2 * STEP], v3 = p[3 * STEP];
        #pragma unroll
        for (int t = 0; t < LOOP; ++t) {
            float v4 = p[(t + 4) * STEP];
            p[t * STEP] = ((v0 + v4) + 2.0f * (v1 + v3) + 3.0f * v2) * inv9;
            v0 = v1; v1 = v2; v2 = v3; v3 = v4;
        }
    }
    __syncthreads();
}

// Final 5-tap fused avg-avg along x, reading the embedding and writing the
// compact 13^3 result straight to global memory.
__device__ __forceinline__ void avg5_final(const float* __restrict__ buf,
                                           float* __restrict__ gdst) {
    const float inv9 = 1.0f / 9.0f;
    for (int line = threadIdx.x; line < 169; line += blockDim.x) {
        int u = line % 13;
        int v = line / 13;
        const float* p = buf + v * 17 + u;     // taps along x: stride 323
        float* q = gdst + v * 13 + u;          // out stride along x: 169
        float v0 = p[0], v1 = p[323], v2 = p[646], v3 = p[969];
        #pragma unroll
        for (int t = 0; t < 13; ++t) {
            float v4 = p[(t + 4) * 323];
            q[t * 169] = ((v0 + v4) + 2.0f * (v1 + v3) + 3.0f * v2) * inv9;
            v0 = v1; v1 = v2; v2 = v3; v3 = v4;
        }
    }
}

// Fused edge-pad + maxpool-z: reads 13^3 staging C, writes (19,19,17) into
// buf at strides (323,17,1). Clamps fold at compile time.
__device__ __forceinline__ void padmax_z(const float* __restrict__ C,
                                         float* __restrict__ buf) {
    for (int line = threadIdx.x; line < PD * PD; line += blockDim.x) {
        int y = line % PD;
        int x = line / PD;
        int sx = min(max(x - 3, 0), LD - 1);
        int sy = min(max(y - 3, 0), LD - 1);
        const float* src = C + (sx * LD + sy) * LD;
        float s[LD];
        #pragma unroll
        for (int z = 0; z < LD; ++z) s[z] = src[z];
        float* q = buf + x * 323 + y * 17;
        #pragma unroll
        for (int t = 0; t < 17; ++t) {
            const int c0 = (t - 3 < 0) ? 0 : ((t - 3 > 12) ? 12 : t - 3);
            const int c1 = (t - 2 < 0) ? 0 : ((t - 2 > 12) ? 12 : t - 2);
            const int c2 = (t - 1 < 0) ? 0 : ((t - 1 > 12) ? 12 : t - 1);
            q[t] = fmaxf(s[c0], fmaxf(s[c1], s[c2]));
        }
    }
    __syncthreads();
}

// Full smooth from staged 13^3 volume C to global gdst.
__device__ __forceinline__ void smooth(const float* C, float* buf,
                                       float* __restrict__ gdst) {
    padmax_z(C, buf);                                   // -> (19,19,17)
    max3_ip<323, 17, 323,  1,  17, 17>(buf);            // max y -> (19,17,17)
    max3_ip<289, 17,  17,  1, 323, 17>(buf);            // max x -> (17,17,17)
    avg5_ip<289, 17, 323, 17,   1, 13>(buf);            // avg2 z -> (17,17,13)
    avg5_ip<221, 13, 323,  1,  17, 13>(buf);            // avg2 y -> (17,13,13)
    avg5_final(buf, gdst);                              // avg2 x -> 13^3 global
}

// Kernel 1: s1[n] = smooth(alpha1 + alpha0 * cost[n])
__global__ void __launch_bounds__(384)
k_stage1(const float* __restrict__ cost, const float* __restrict__ alpha) {
    extern __shared__ float sm[];
    float* C   = sm;            // C_SZ floats
    float* buf = sm + C_SZ;     // BUF_SZ floats
    int n = blockIdx.x;
    float a0 = alpha[0], a1 = alpha[1];
    const float* src = cost + (size_t)n * VOL;
    for (int v = threadIdx.x; v < VOL; v += blockDim.x)
        C[v] = a1 + a0 * src[v];
    __syncthreads();
    smooth(C, buf, g_s1 + (size_t)n * VOLP);
}

#define GATH(c) (w0*f0.c + w1*f1.c + w2*f2.c + w3*f3.c + \
                 w4*f4.c + w5*f5.c + w6*f6.c + w7*f7.c)

// Kernel 2: gather s1 over knn -> combine with original cost -> smooth -> s2
__global__ void __launch_bounds__(384)
k_stage2(const float* __restrict__ cost, const int* __restrict__ knn,
         const float* __restrict__ dist, const float* __restrict__ alpha) {
    extern __shared__ float sm[];
    float* C   = sm;
    float* buf = sm + C_SZ;
    __shared__ float ws[KNB];
    __shared__ int   nb[KNB];
    int n = blockIdx.x;
    if (threadIdx.x < KNB) {
        ws[threadIdx.x] = __expf(-dist[n * KNB + threadIdx.x] * 0.005f); // 1/(2*SIGMA^2)
        nb[threadIdx.x] = knn[n * KNB + threadIdx.x];
    }
    __syncthreads();
    float w0 = ws[0], w1 = ws[1], w2 = ws[2], w3 = ws[3];
    float w4 = ws[4], w5 = ws[5], w6 = ws[6], w7 = ws[7];
    float inv_norm = 1.0f / (w0 + w1 + w2 + w3 + w4 + w5 + w6 + w7);
    const float4* p0 = (const float4*)(g_s1 + (size_t)nb[0] * VOLP);
    const float4* p1 = (const float4*)(g_s1 + (size_t)nb[1] * VOLP);
    const float4* p2 = (const float4*)(g_s1 + (size_t)nb[2] * VOLP);
    const float4* p3 = (const float4*)(g_s1 + (size_t)nb[3] * VOLP);
    const float4* p4 = (const float4*)(g_s1 + (size_t)nb[4] * VOLP);
    const float4* p5 = (const float4*)(g_s1 + (size_t)nb[5] * VOLP);
    const float4* p6 = (const float4*)(g_s1 + (size_t)nb[6] * VOLP);
    const float4* p7 = (const float4*)(g_s1 + (size_t)nb[7] * VOLP);
    float a0 = alpha[0], a1 = alpha[1], a2 = alpha[2], a3 = alpha[3], a4 = alpha[4];
    float k1 = a2 * a0, k2 = a2 * a1 + a4, k3 = a3 * inv_norm;
    const float* src = cost + (size_t)n * VOL;
    float4* Cv = (float4*)C;
    for (int v = threadIdx.x; v < VOL / 4; v += blockDim.x) {   // 549 float4s
        float4 f0 = p0[v], f1 = p1[v], f2 = p2[v], f3 = p3[v];
        float4 f4 = p4[v], f5 = p5[v], f6 = p6[v], f7 = p7[v];
        const float* cs = src + 4 * v;
        float4 r;
        r.x = k2 + k1 * cs[0] + k3 * GATH(x);
        r.y = k2 + k1 * cs[1] + k3 * GATH(y);
        r.z = k2 + k1 * cs[2] + k3 * GATH(z);
        r.w = k2 + k1 * cs[3] + k3 * GATH(w);
        Cv[v] = r;
    }
    if (threadIdx.x == 0) {  // tail element 2196
        const int v = VOL - 1;
        const float* b = g_s1;
        float g = w0 * b[(size_t)nb[0] * VOLP + v] + w1 * b[(size_t)nb[1] * VOLP + v]
                + w2 * b[(size_t)nb[2] * VOLP + v] + w3 * b[(size_t)nb[3] * VOLP + v]
                + w4 * b[(size_t)nb[4] * VOLP + v] + w5 * b[(size_t)nb[5] * VOLP + v]
                + w6 * b[(size_t)nb[6] * VOLP + v] + w7 * b[(size_t)nb[7] * VOLP + v];
        C[v] = k2 + k1 * src[v] + k3 * g;
    }
    __syncthreads();
    smooth(C, buf, g_s2 + (size_t)n * VOLP);
}

// Kernel 3: out[n] = alpha5 * (gather s2 over knn) / norm
__global__ void __launch_bounds__(256)
k_stage3(const int* __restrict__ knn, const float* __restrict__ dist,
         const float* __restrict__ alpha, float* __restrict__ out) {
    __shared__ float ws[KNB];
    __shared__ int   nb[KNB];
    int n = blockIdx.x;
    if (threadIdx.x < KNB) {
        ws[threadIdx.x] = __expf(-dist[n * KNB + threadIdx.x] * 0.005f);
        nb[threadIdx.x] = knn[n * KNB + threadIdx.x];
    }
    __syncthreads();
    float w0 = ws[0], w1 = ws[1], w2 = ws[2], w3 = ws[3];
    float w4 = ws[4], w5 = ws[5], w6 = ws[6], w7 = ws[7];
    float inv_norm = 1.0f / (w0 + w1 + w2 + w3 + w4 + w5 + w6 + w7);
    float s = alpha[5] * inv_norm;
    const float4* p0 = (const float4*)(g_s2 + (size_t)nb[0] * VOLP);
    const float4* p1 = (const float4*)(g_s2 + (size_t)nb[1] * VOLP);
    const float4* p2 = (const float4*)(g_s2 + (size_t)nb[2] * VOLP);
    const float4* p3 = (const float4*)(g_s2 + (size_t)nb[3] * VOLP);
    const float4* p4 = (const float4*)(g_s2 + (size_t)nb[4] * VOLP);
    const float4* p5 = (const float4*)(g_s2 + (size_t)nb[5] * VOLP);
    const float4* p6 = (const float4*)(g_s2 + (size_t)nb[6] * VOLP);
    const float4* p7 = (const float4*)(g_s2 + (size_t)nb[7] * VOLP);
    float* dst = out + (size_t)n * VOL;
    for (int v = threadIdx.x; v < VOL / 4; v += blockDim.x) {
        float4 f0 = p0[v], f1 = p1[v], f2 = p2[v], f3 = p3[v];
        float4 f4 = p4[v], f5 = p5[v], f6 = p6[v], f7 = p7[v];
        float* q = dst + 4 * v;
        q[0] = s * GATH(x);
        q[1] = s * GATH(y);
        q[2] = s * GATH(z);
        q[3] = s * GATH(w);
    }
    if (threadIdx.x == 0) {  // tail element 2196
        const int v = VOL - 1;
        const float* b = g_s2;
        float g = w0 * b[(size_t)nb[0] * VOLP + v] + w1 * b[(size_t)nb[1] * VOLP + v]
                + w2 * b[(size_t)nb[2] * VOLP + v] + w3 * b[(size_t)nb[3] * VOLP + v]
                + w4 * b[(size_t)nb[4] * VOLP + v] + w5 * b[(size_t)nb[5] * VOLP + v]
                + w6 * b[(size_t)nb[6] * VOLP + v] + w7 * b[(size_t)nb[7] * VOLP + v];
        dst[v] = s * g;
    }
}

extern "C" void kernel_launch(void* const* d_in, const int* in_sizes, int n_in,
                              void* d_out, int out_size) {
    const float* cost  = (const float*)d_in[0];
    const int*   knn   = (const int*)d_in[1];
    const float* dist  = (const float*)d_in[2];
    const float* alpha = (const float*)d_in[3];
    float* out = (float*)d_out;

    k_stage1<<<NN, 384, SMEMB>>>(cost, alpha);
    k_stage2<<<NN, 384, SMEMB>>>(cost, knn, dist, alpha);
    k_stage3<<<NN, 256>>>(knn, dist, alpha, out);
}

// round 9
// speedup vs baseline: 1.4255x; 1.2393x over previous
#include <cuda_runtime.h>
#include <cuda_fp16.h>
#include <cstdint>

// Problem constants (fixed by the dataset)
#define NN     10000
#define LD     13
#define VOL    2197
#define VOLP   2208         // padded node stride (16B-aligned gathers)
#define KNB    8
#define PD     19

// half2 word-buffer layout: (x, y, zpair) strides in half2 words
#define WX     171          // = 19*9
#define WY     9
#define BW     3249         // 19*171 words
#define C_SZ   2197
#define SMEMB  (C_SZ * 4 + BW * 4)   // 8788 + 12996 = 21784 B

static __device__ float g_s1[(size_t)NN * VOLP];
static __device__ float g_s2[(size_t)NN * VOLP];

// ---- smooth chain on fp16 half2-packed z-pairs, all in-place in B ----------

// pad + maxpool-z: read fp32 C (13^3), emit (19,19,17) z-maxes packed as half2.
__device__ __forceinline__ void padmax_z(const float* __restrict__ C,
                                         __half2* __restrict__ B) {
    for (int line = threadIdx.x; line < PD * PD; line += blockDim.x) {
        int y = line % PD;
        int x = line / PD;
        int sx = min(max(x - 3, 0), LD - 1);
        int sy = min(max(y - 3, 0), LD - 1);
        const float* src = C + (sx * LD + sy) * LD;
        float s[LD];
        #pragma unroll
        for (int z = 0; z < LD; ++z) s[z] = src[z];
        float m[17];
        #pragma unroll
        for (int t = 0; t < 17; ++t) {
            const int c0 = (t - 3 < 0) ? 0 : ((t - 3 > 12) ? 12 : t - 3);
            const int c1 = (t - 2 < 0) ? 0 : ((t - 2 > 12) ? 12 : t - 2);
            const int c2 = (t - 1 < 0) ? 0 : ((t - 1 > 12) ? 12 : t - 1);
            m[t] = fmaxf(s[c0], fmaxf(s[c1], s[c2]));
        }
        __half2* q = B + x * WX + y * WY;
        #pragma unroll
        for (int zp = 0; zp < 8; ++zp)
            q[zp] = __floats2half2_rn(m[2 * zp], m[2 * zp + 1]);
        q[8] = __floats2half2_rn(m[16], 0.0f);
    }
    __syncthreads();
}

// max along y: (19,19,9w) -> (19,17,9w), in-place. fp16 max is exact.
__device__ __forceinline__ void max_y(__half2* B) {
    for (int line = threadIdx.x; line < 19 * 9; line += blockDim.x) {
        int zp = line % 9;
        int x  = line / 9;
        __half2* p = B + x * WX + zp;
        __half2 v0 = p[0], v1 = p[WY];
        #pragma unroll
        for (int t = 0; t < 17; ++t) {
            __half2 v2 = p[(t + 2) * WY];
            p[t * WY] = __hmax2(v0, __hmax2(v1, v2));
            v0 = v1; v1 = v2;
        }
    }
    __syncthreads();
}

// max along x: (19,17,9w) -> (17,17,9w), in-place.
__device__ __forceinline__ void max_x(__half2* B) {
    for (int line = threadIdx.x; line < 17 * 9; line += blockDim.x) {
        int zp = line % 9;
        int y  = line / 9;
        __half2* p = B + y * WY + zp;
        __half2 v0 = p[0], v1 = p[WX];
        #pragma unroll
        for (int t = 0; t < 17; ++t) {
            __half2 v2 = p[(t + 2) * WX];
            p[t * WX] = __hmax2(v0, __hmax2(v1, v2));
            v0 = v1; v1 = v2;
        }
    }
    __syncthreads();
}

// fused avg-avg along z (5-tap 1,2,3,2,1 / 9): z 17 -> 13 (7 words), in-place.
__device__ __forceinline__ void avg5_z(__half2* B) {
    const float inv9 = 1.0f / 9.0f;
    for (int line = threadIdx.x; line < 17 * 17; line += blockDim.x) {
        int y = line % 17;
        int x = line / 17;
        __half2* p = B + x * WX + y * WY;
        float s[18];
        #pragma unroll
        for (int zp = 0; zp < 9; ++zp) {
            float2 f = __half22float2(p[zp]);
            s[2 * zp] = f.x; s[2 * zp + 1] = f.y;
        }
        float o[13];
        #pragma unroll
        for (int t = 0; t < 13; ++t)
            o[t] = ((s[t] + s[t + 4]) + 2.0f * (s[t + 1] + s[t + 3])
                    + 3.0f * s[t + 2]) * inv9;
        #pragma unroll
        for (int zp = 0; zp < 6; ++zp)
            p[zp] = __floats2half2_rn(o[2 * zp], o[2 * zp + 1]);
        p[6] = __floats2half2_rn(o[12], 0.0f);
    }
    __syncthreads();
}

// fused avg-avg along y: (17,17,7w) -> (17,13,7w), in-place, fp32 math.
__device__ __forceinline__ void avg5_y(__half2* B) {
    const float inv9 = 1.0f / 9.0f;
    for (int line = threadIdx.x; line < 17 * 7; line += blockDim.x) {
        int zp = line % 7;
        int x  = line / 7;
        __half2* p = B + x * WX + zp;
        float2 v0 = __half22float2(p[0]);
        float2 v1 = __half22float2(p[WY]);
        float2 v2 = __half22float2(p[2 * WY]);
        float2 v3 = __half22float2(p[3 * WY]);
        #pragma unroll
        for (int t = 0; t < 13; ++t) {
            float2 v4 = __half22float2(p[(t + 4) * WY]);
            float rx = ((v0.x + v4.x) + 2.0f * (v1.x + v3.x) + 3.0f * v2.x) * inv9;
            float ry = ((v0.y + v4.y) + 2.0f * (v1.y + v3.y) + 3.0f * v2.y) * inv9;
            p[t * WY] = __floats2half2_rn(rx, ry);
            v0 = v1; v1 = v2; v2 = v3; v3 = v4;
        }
    }
    __syncthreads();
}

// fused avg-avg along x: (17,13,7w) -> 13^3 fp32 straight to global.
__device__ __forceinline__ void avg5_x_final(const __half2* __restrict__ B,
                                             float* __restrict__ gdst) {
    const float inv9 = 1.0f / 9.0f;
    for (int line = threadIdx.x; line < 13 * 7; line += blockDim.x) {
        int zp = line % 7;
        int y  = line / 7;
        const __half2* p = B + y * WY + zp;
        float* q = gdst + y * LD + 2 * zp;
        float2 v0 = __half22float2(p[0]);
        float2 v1 = __half22float2(p[WX]);
        float2 v2 = __half22float2(p[2 * WX]);
        float2 v3 = __half22float2(p[3 * WX]);
        #pragma unroll
        for (int t = 0; t < 13; ++t) {
            float2 v4 = __half22float2(p[(t + 4) * WX]);
            float rx = ((v0.x + v4.x) + 2.0f * (v1.x + v3.x) + 3.0f * v2.x) * inv9;
            float ry = ((v0.y + v4.y) + 2.0f * (v1.y + v3.y) + 3.0f * v2.y) * inv9;
            q[t * 169] = rx;
            if (zp < 6) q[t * 169 + 1] = ry;   // zp=6 high half = z13 pad
            v0 = v1; v1 = v2; v2 = v3; v3 = v4;
        }
    }
}

__device__ __forceinline__ void smooth(const float* C, __half2* B,
                                       float* __restrict__ gdst) {
    padmax_z(C, B);
    max_y(B);
    max_x(B);
    avg5_z(B);
    avg5_y(B);
    avg5_x_final(B, gdst);
}

// Kernel 1: s1[n] = smooth(alpha1 + alpha0 * cost[n])
__global__ void __launch_bounds__(384)
k_stage1(const float* __restrict__ cost, const float* __restrict__ alpha) {
    extern __shared__ float sm[];
    float*   C = sm;
    __half2* B = (__half2*)(sm + C_SZ);
    int n = blockIdx.x;
    float a0 = alpha[0], a1 = alpha[1];
    const float* src = cost + (size_t)n * VOL;
    for (int v = threadIdx.x; v < VOL; v += blockDim.x)
        C[v] = a1 + a0 * src[v];
    __syncthreads();
    smooth(C, B, g_s1 + (size_t)n * VOLP);
}

#define GATH(c) (w0*f0.c + w1*f1.c + w2*f2.c + w3*f3.c + \
                 w4*f4.c + w5*f5.c + w6*f6.c + w7*f7.c)

// Kernel 2: gather s1 over knn -> combine with cost -> smooth -> s2
__global__ void __launch_bounds__(384)
k_stage2(const float* __restrict__ cost, const int* __restrict__ knn,
         const float* __restrict__ dist, const float* __restrict__ alpha) {
    extern __shared__ float sm[];
    float*   C = sm;
    __half2* B = (__half2*)(sm + C_SZ);
    __shared__ float ws[KNB];
    __shared__ int   nb[KNB];
    int n = blockIdx.x;
    if (threadIdx.x < KNB) {
        ws[threadIdx.x] = __expf(-dist[n * KNB + threadIdx.x] * 0.005f);
        nb[threadIdx.x] = knn[n * KNB + threadIdx.x];
    }
    __syncthreads();
    float w0 = ws[0], w1 = ws[1], w2 = ws[2], w3 = ws[3];
    float w4 = ws[4], w5 = ws[5], w6 = ws[6], w7 = ws[7];
    float inv_norm = 1.0f / (w0 + w1 + w2 + w3 + w4 + w5 + w6 + w7);
    const float4* p0 = (const float4*)(g_s1 + (size_t)nb[0] * VOLP);
    const float4* p1 = (const float4*)(g_s1 + (size_t)nb[1] * VOLP);
    const float4* p2 = (const float4*)(g_s1 + (size_t)nb[2] * VOLP);
    const float4* p3 = (const float4*)(g_s1 + (size_t)nb[3] * VOLP);
    const float4* p4 = (const float4*)(g_s1 + (size_t)nb[4] * VOLP);
    const float4* p5 = (const float4*)(g_s1 + (size_t)nb[5] * VOLP);
    const float4* p6 = (const float4*)(g_s1 + (size_t)nb[6] * VOLP);
    const float4* p7 = (const float4*)(g_s1 + (size_t)nb[7] * VOLP);
    float a0 = alpha[0], a1 = alpha[1], a2 = alpha[2], a3 = alpha[3], a4 = alpha[4];
    float k1 = a2 * a0, k2 = a2 * a1 + a4, k3 = a3 * inv_norm;
    const float* src = cost + (size_t)n * VOL;
    float4* Cv = (float4*)C;
    for (int v = threadIdx.x; v < VOL / 4; v += blockDim.x) {
        float4 f0 = p0[v], f1 = p1[v], f2 = p2[v], f3 = p3[v];
        float4 f4 = p4[v], f5 = p5[v], f6 = p6[v], f7 = p7[v];
        const float* cs = src + 4 * v;
        float4 r;
        r.x = k2 + k1 * cs[0] + k3 * GATH(x);
        r.y = k2 + k1 * cs[1] + k3 * GATH(y);
        r.z = k2 + k1 * cs[2] + k3 * GATH(z);
        r.w = k2 + k1 * cs[3] + k3 * GATH(w);
        Cv[v] = r;
    }
    if (threadIdx.x == 0) {
        const int v = VOL - 1;
        const float* b = g_s1;
        float g = w0 * b[(size_t)nb[0] * VOLP + v] + w1 * b[(size_t)nb[1] * VOLP + v]
                + w2 * b[(size_t)nb[2] * VOLP + v] + w3 * b[(size_t)nb[3] * VOLP + v]
                + w4 * b[(size_t)nb[4] * VOLP + v] + w5 * b[(size_t)nb[5] * VOLP + v]
                + w6 * b[(size_t)nb[6] * VOLP + v] + w7 * b[(size_t)nb[7] * VOLP + v];
        C[v] = k2 + k1 * src[v] + k3 * g;
    }
    __syncthreads();
    smooth(C, B, g_s2 + (size_t)n * VOLP);
}

// Kernel 3: out[n] = alpha5 * (gather s2 over knn) / norm
__global__ void __launch_bounds__(256)
k_stage3(const int* __restrict__ knn, const float* __restrict__ dist,
         const float* __restrict__ alpha, float* __restrict__ out) {
    __shared__ float ws[KNB];
    __shared__ int   nb[KNB];
    int n = blockIdx.x;
    if (threadIdx.x < KNB) {
        ws[threadIdx.x] = __expf(-dist[n * KNB + threadIdx.x] * 0.005f);
        nb[threadIdx.x] = knn[n * KNB + threadIdx.x];
    }
    __syncthreads();
    float w0 = ws[0], w1 = ws[1], w2 = ws[2], w3 = ws[3];
    float w4 = ws[4], w5 = ws[5], w6 = ws[6], w7 = ws[7];
    float inv_norm = 1.0f / (w0 + w1 + w2 + w3 + w4 + w5 + w6 + w7);
    float s = alpha[5] * inv_norm;
    const float4* p0 = (const float4*)(g_s2 + (size_t)nb[0] * VOLP);
    const float4* p1 = (const float4*)(g_s2 + (size_t)nb[1] * VOLP);
    const float4* p2 = (const float4*)(g_s2 + (size_t)nb[2] * VOLP);
    const float4* p3 = (const float4*)(g_s2 + (size_t)nb[3] * VOLP);
    const float4* p4 = (const float4*)(g_s2 + (size_t)nb[4] * VOLP);
    const float4* p5 = (const float4*)(g_s2 + (size_t)nb[5] * VOLP);
    const float4* p6 = (const float4*)(g_s2 + (size_t)nb[6] * VOLP);
    const float4* p7 = (const float4*)(g_s2 + (size_t)nb[7] * VOLP);
    float* dst = out + (size_t)n * VOL;
    for (int v = threadIdx.x; v < VOL / 4; v += blockDim.x) {
        float4 f0 = p0[v], f1 = p1[v], f2 = p2[v], f3 = p3[v];
        float4 f4 = p4[v], f5 = p5[v], f6 = p6[v], f7 = p7[v];
        float* q = dst + 4 * v;
        q[0] = s * GATH(x);
        q[1] = s * GATH(y);
        q[2] = s * GATH(z);
        q[3] = s * GATH(w);
    }
    if (threadIdx.x == 0) {
        const int v = VOL - 1;
        const float* b = g_s2;
        float g = w0 * b[(size_t)nb[0] * VOLP + v] + w1 * b[(size_t)nb[1] * VOLP + v]
                + w2 * b[(size_t)nb[2] * VOLP + v] + w3 * b[(size_t)nb[3] * VOLP + v]
                + w4 * b[(size_t)nb[4] * VOLP + v] + w5 * b[(size_t)nb[5] * VOLP + v]
                + w6 * b[(size_t)nb[6] * VOLP + v] + w7 * b[(size_t)nb[7] * VOLP + v];
        dst[v] = s * g;
    }
}

extern "C" void kernel_launch(void* const* d_in, const int* in_sizes, int n_in,
                              void* d_out, int out_size) {
    const float* cost  = (const float*)d_in[0];
    const int*   knn   = (const int*)d_in[1];
    const float* dist  = (const float*)d_in[2];
    const float* alpha = (const float*)d_in[3];
    float* out = (float*)d_out;

    k_stage1<<<NN, 384, SMEMB>>>(cost, alpha);
    k_stage2<<<NN, 384, SMEMB>>>(cost, knn, dist, alpha);
    k_stage3<<<NN, 256>>>(knn, dist, alpha, out);
}

// round 10
// speedup vs baseline: 1.7372x; 1.2187x over previous
#include <cuda_runtime.h>
#include <cuda_fp16.h>
#include <cstdint>

// Problem constants (fixed by the dataset)
#define NN     10000
#define LD     13
#define VOL    2197
#define VOLP   2208         // padded node stride (16B-aligned uint4 = 8 halves)
#define KNB    8
#define PD     19

// half2 word-buffer layout: (x, y, zpair) strides in half2 words
#define WX     171          // = 19*9
#define WY     9
#define BW     3249         // 19*171 words
#define C_SZ   2208         // fp32 staging (padded: stage2 writes up to 2207)
#define SMEMB  (C_SZ * 4 + BW * 4)   // 8832 + 12996 = 21828 B

static __device__ __half g_s1[(size_t)NN * VOLP];   // fp16 inter-stage arrays
static __device__ __half g_s2[(size_t)NN * VOLP];   // (44 MB each -> L2-resident)

// ---- smooth chain on fp16 half2-packed z-pairs, all in-place in B ----------

__device__ __forceinline__ void padmax_z(const float* __restrict__ C,
                                         __half2* __restrict__ B) {
    for (int line = threadIdx.x; line < PD * PD; line += blockDim.x) {
        int y = line % PD;
        int x = line / PD;
        int sx = min(max(x - 3, 0), LD - 1);
        int sy = min(max(y - 3, 0), LD - 1);
        const float* src = C + (sx * LD + sy) * LD;
        float s[LD];
        #pragma unroll
        for (int z = 0; z < LD; ++z) s[z] = src[z];
        float m[17];
        #pragma unroll
        for (int t = 0; t < 17; ++t) {
            const int c0 = (t - 3 < 0) ? 0 : ((t - 3 > 12) ? 12 : t - 3);
            const int c1 = (t - 2 < 0) ? 0 : ((t - 2 > 12) ? 12 : t - 2);
            const int c2 = (t - 1 < 0) ? 0 : ((t - 1 > 12) ? 12 : t - 1);
            m[t] = fmaxf(s[c0], fmaxf(s[c1], s[c2]));
        }
        __half2* q = B + x * WX + y * WY;
        #pragma unroll
        for (int zp = 0; zp < 8; ++zp)
            q[zp] = __floats2half2_rn(m[2 * zp], m[2 * zp + 1]);
        q[8] = __floats2half2_rn(m[16], 0.0f);
    }
    __syncthreads();
}

__device__ __forceinline__ void max_y(__half2* B) {
    for (int line = threadIdx.x; line < 19 * 9; line += blockDim.x) {
        int zp = line % 9;
        int x  = line / 9;
        __half2* p = B + x * WX + zp;
        __half2 v0 = p[0], v1 = p[WY];
        #pragma unroll
        for (int t = 0; t < 17; ++t) {
            __half2 v2 = p[(t + 2) * WY];
            p[t * WY] = __hmax2(v0, __hmax2(v1, v2));
            v0 = v1; v1 = v2;
        }
    }
    __syncthreads();
}

__device__ __forceinline__ void max_x(__half2* B) {
    for (int line = threadIdx.x; line < 17 * 9; line += blockDim.x) {
        int zp = line % 9;
        int y  = line / 9;
        __half2* p = B + y * WY + zp;
        __half2 v0 = p[0], v1 = p[WX];
        #pragma unroll
        for (int t = 0; t < 17; ++t) {
            __half2 v2 = p[(t + 2) * WX];
            p[t * WX] = __hmax2(v0, __hmax2(v1, v2));
            v0 = v1; v1 = v2;
        }
    }
    __syncthreads();
}

__device__ __forceinline__ void avg5_z(__half2* B) {
    const float inv9 = 1.0f / 9.0f;
    for (int line = threadIdx.x; line < 17 * 17; line += blockDim.x) {
        int y = line % 17;
        int x = line / 17;
        __half2* p = B + x * WX + y * WY;
        float s[18];
        #pragma unroll
        for (int zp = 0; zp < 9; ++zp) {
            float2 f = __half22float2(p[zp]);
            s[2 * zp] = f.x; s[2 * zp + 1] = f.y;
        }
        float o[13];
        #pragma unroll
        for (int t = 0; t < 13; ++t)
            o[t] = ((s[t] + s[t + 4]) + 2.0f * (s[t + 1] + s[t + 3])
                    + 3.0f * s[t + 2]) * inv9;
        #pragma unroll
        for (int zp = 0; zp < 6; ++zp)
            p[zp] = __floats2half2_rn(o[2 * zp], o[2 * zp + 1]);
        p[6] = __floats2half2_rn(o[12], 0.0f);
    }
    __syncthreads();
}

__device__ __forceinline__ void avg5_y(__half2* B) {
    const float inv9 = 1.0f / 9.0f;
    for (int line = threadIdx.x; line < 17 * 7; line += blockDim.x) {
        int zp = line % 7;
        int x  = line / 7;
        __half2* p = B + x * WX + zp;
        float2 v0 = __half22float2(p[0]);
        float2 v1 = __half22float2(p[WY]);
        float2 v2 = __half22float2(p[2 * WY]);
        float2 v3 = __half22float2(p[3 * WY]);
        #pragma unroll
        for (int t = 0; t < 13; ++t) {
            float2 v4 = __half22float2(p[(t + 4) * WY]);
            float rx = ((v0.x + v4.x) + 2.0f * (v1.x + v3.x) + 3.0f * v2.x) * inv9;
            float ry = ((v0.y + v4.y) + 2.0f * (v1.y + v3.y) + 3.0f * v2.y) * inv9;
            p[t * WY] = __floats2half2_rn(rx, ry);
            v0 = v1; v1 = v2; v2 = v3; v3 = v4;
        }
    }
    __syncthreads();
}

// final fused avg-avg along x: (17,13,7w) -> 13^3, written as fp16 to global.
__device__ __forceinline__ void avg5_x_final(const __half2* __restrict__ B,
                                             __half* __restrict__ gdst) {
    const float inv9 = 1.0f / 9.0f;
    for (int line = threadIdx.x; line < 13 * 7; line += blockDim.x) {
        int zp = line % 7;
        int y  = line / 7;
        const __half2* p = B + y * WY + zp;
        __half* q = gdst + y * LD + 2 * zp;
        float2 v0 = __half22float2(p[0]);
        float2 v1 = __half22float2(p[WX]);
        float2 v2 = __half22float2(p[2 * WX]);
        float2 v3 = __half22float2(p[3 * WX]);
        #pragma unroll
        for (int t = 0; t < 13; ++t) {
            float2 v4 = __half22float2(p[(t + 4) * WX]);
            float rx = ((v0.x + v4.x) + 2.0f * (v1.x + v3.x) + 3.0f * v2.x) * inv9;
            float ry = ((v0.y + v4.y) + 2.0f * (v1.y + v3.y) + 3.0f * v2.y) * inv9;
            q[t * 169] = __float2half_rn(rx);
            if (zp < 6) q[t * 169 + 1] = __float2half_rn(ry);
            v0 = v1; v1 = v2; v2 = v3; v3 = v4;
        }
    }
}

__device__ __forceinline__ void smooth(const float* C, __half2* B,
                                       __half* __restrict__ gdst) {
    padmax_z(C, B);
    max_y(B);
    max_x(B);
    avg5_z(B);
    avg5_y(B);
    avg5_x_final(B, gdst);
}

// unpack 8 halves (one uint4) to fp32
__device__ __forceinline__ void h8(const uint4 u, float* f) {
    float2 a = __half22float2(*(const __half2*)&u.x);
    float2 b = __half22float2(*(const __half2*)&u.y);
    float2 c = __half22float2(*(const __half2*)&u.z);
    float2 d = __half22float2(*(const __half2*)&u.w);
    f[0] = a.x; f[1] = a.y; f[2] = b.x; f[3] = b.y;
    f[4] = c.x; f[5] = c.y; f[6] = d.x; f[7] = d.y;
}

// Kernel 1: s1[n] = smooth(alpha1 + alpha0 * cost[n])
__global__ void __launch_bounds__(384)
k_stage1(const float* __restrict__ cost, const float* __restrict__ alpha) {
    extern __shared__ float sm[];
    float*   C = sm;
    __half2* B = (__half2*)(sm + C_SZ);
    int n = blockIdx.x;
    float a0 = alpha[0], a1 = alpha[1];
    const float* src = cost + (size_t)n * VOL;
    for (int v = threadIdx.x; v < VOL; v += blockDim.x)
        C[v] = a1 + a0 * src[v];
    __syncthreads();
    smooth(C, B, g_s1 + (size_t)n * VOLP);
}

// Kernel 2: gather s1 over knn -> combine with cost -> smooth -> s2
__global__ void __launch_bounds__(384)
k_stage2(const float* __restrict__ cost, const int* __restrict__ knn,
         const float* __restrict__ dist, const float* __restrict__ alpha) {
    extern __shared__ float sm[];
    float*   C = sm;
    __half2* B = (__half2*)(sm + C_SZ);
    __shared__ float ws[KNB];
    __shared__ int   nb[KNB];
    int n = blockIdx.x;
    if (threadIdx.x < KNB) {
        ws[threadIdx.x] = __expf(-dist[n * KNB + threadIdx.x] * 0.005f);
        nb[threadIdx.x] = knn[n * KNB + threadIdx.x];
    }
    __syncthreads();
    float w[KNB];
    #pragma unroll
    for (int k = 0; k < KNB; ++k) w[k] = ws[k];
    float norm = 0.0f;
    #pragma unroll
    for (int k = 0; k < KNB; ++k) norm += w[k];
    const uint4* p[KNB];
    #pragma unroll
    for (int k = 0; k < KNB; ++k)
        p[k] = (const uint4*)(g_s1 + (size_t)nb[k] * VOLP);
    float a0 = alpha[0], a1 = alpha[1], a2 = alpha[2], a3 = alpha[3], a4 = alpha[4];
    float k1 = a2 * a0, k2 = a2 * a1 + a4, k3 = a3 / norm;
    const float* src = cost + (size_t)n * VOL;
    // 276 uint4 = 2208 halves per neighbor (pad lanes produce garbage in
    // C[2197..2207], which the smooth never reads).
    for (int v = threadIdx.x; v < VOLP / 8; v += blockDim.x) {
        float acc[8] = {0, 0, 0, 0, 0, 0, 0, 0};
        #pragma unroll
        for (int k = 0; k < KNB; ++k) {
            float f[8];
            h8(p[k][v], f);
            #pragma unroll
            for (int j = 0; j < 8; ++j) acc[j] += w[k] * f[j];
        }
        int base = 8 * v;
        float r[8];
        #pragma unroll
        for (int j = 0; j < 8; ++j) {
            float cs = (base + j < VOL) ? src[base + j] : 0.0f;
            r[j] = k2 + k1 * cs + k3 * acc[j];
        }
        float4* Cv = (float4*)(C + base);
        Cv[0] = make_float4(r[0], r[1], r[2], r[3]);
        Cv[1] = make_float4(r[4], r[5], r[6], r[7]);
    }
    __syncthreads();
    smooth(C, B, g_s2 + (size_t)n * VOLP);
}

// Kernel 3: out[n] = alpha5 * (gather s2 over knn) / norm
__global__ void __launch_bounds__(256)
k_stage3(const int* __restrict__ knn, const float* __restrict__ dist,
         const float* __restrict__ alpha, float* __restrict__ out) {
    __shared__ float ws[KNB];
    __shared__ int   nb[KNB];
    int n = blockIdx.x;
    if (threadIdx.x < KNB) {
        ws[threadIdx.x] = __expf(-dist[n * KNB + threadIdx.x] * 0.005f);
        nb[threadIdx.x] = knn[n * KNB + threadIdx.x];
    }
    __syncthreads();
    float w[KNB];
    #pragma unroll
    for (int k = 0; k < KNB; ++k) w[k] = ws[k];
    float norm = 0.0f;
    #pragma unroll
    for (int k = 0; k < KNB; ++k) norm += w[k];
    float s = alpha[5] / norm;
    const uint4* p[KNB];
    #pragma unroll
    for (int k = 0; k < KNB; ++k)
        p[k] = (const uint4*)(g_s2 + (size_t)nb[k] * VOLP);
    float* dst = out + (size_t)n * VOL;
    // full uint4 groups: 274 * 8 = 2192 elements
    for (int v = threadIdx.x; v < VOL / 8; v += blockDim.x) {
        float acc[8] = {0, 0, 0, 0, 0, 0, 0, 0};
        #pragma unroll
        for (int k = 0; k < KNB; ++k) {
            float f[8];
            h8(p[k][v], f);
            #pragma unroll
            for (int j = 0; j < 8; ++j) acc[j] += w[k] * f[j];
        }
        float* q = dst + 8 * v;
        #pragma unroll
        for (int j = 0; j < 8; ++j) q[j] = s * acc[j];
    }
    // tail elements 2192..2196 (exact: no writes past this node's region)
    if (threadIdx.x < VOL - (VOL / 8) * 8) {
        int idx = (VOL / 8) * 8 + threadIdx.x;
        float acc = 0.0f;
        #pragma unroll
        for (int k = 0; k < KNB; ++k)
            acc += w[k] * __half2float(g_s2[(size_t)nb[k] * VOLP + idx]);
        dst[idx] = s * acc;
    }
}

extern "C" void kernel_launch(void* const* d_in, const int* in_sizes, int n_in,
                              void* d_out, int out_size) {
    const float* cost  = (const float*)d_in[0];
    const int*   knn   = (const int*)d_in[1];
    const float* dist  = (const float*)d_in[2];
    const float* alpha = (const float*)d_in[3];
    float* out = (float*)d_out;

    k_stage1<<<NN, 384, SMEMB>>>(cost, alpha);
    k_stage2<<<NN, 384, SMEMB>>>(cost, knn, dist, alpha);
    k_stage3<<<NN, 256>>>(knn, dist, alpha, out);
}

// round 11
// speedup vs baseline: 1.8700x; 1.0764x over previous
#include <cuda_runtime.h>
#include <cuda_fp16.h>
#include <cstdint>

// Problem constants (fixed by the dataset)
#define NN     10000
#define LD     13
#define VOL    2197
#define VOLP   2208         // padded node stride (16B-aligned uint4 = 8 halves)
#define KNB    8
#define PD     19

// half2 word-buffer layout: (x, y, zpair) strides in half2 words
#define WX     171          // = 19*9
#define WY     9
#define BW     3249         // 19*171 words per node
#define C_STR  2208         // fp32 staging stride per node (padded)
// two nodes per CTA:
#define SMEMB  (2 * C_STR * 4 + 2 * BW * 4)   // 17664 + 25992 = 43656 B

static __device__ __half g_s1[(size_t)NN * VOLP];   // fp16 inter-stage arrays
static __device__ __half g_s2[(size_t)NN * VOLP];   // (44 MB each -> L2-resident)

// ---- two-node smooth chain, fp16 half2-packed z-pairs, in-place in B -------
// Every pass iterates line over [0, 2*NL); lines >= NL belong to node 1 and
// use buffer/output offsets of one node stride.

__device__ __forceinline__ void padmax_z2(const float* __restrict__ C,
                                          __half2* __restrict__ B) {
    for (int line = threadIdx.x; line < 2 * PD * PD; line += blockDim.x) {
        int l = line, nd = 0;
        if (l >= PD * PD) { l -= PD * PD; nd = 1; }
        int y = l % PD;
        int x = l / PD;
        int sx = min(max(x - 3, 0), LD - 1);
        int sy = min(max(y - 3, 0), LD - 1);
        const float* src = C + nd * C_STR + (sx * LD + sy) * LD;
        float s[LD];
        #pragma unroll
        for (int z = 0; z < LD; ++z) s[z] = src[z];
        float m[17];
        #pragma unroll
        for (int t = 0; t < 17; ++t) {
            const int c0 = (t - 3 < 0) ? 0 : ((t - 3 > 12) ? 12 : t - 3);
            const int c1 = (t - 2 < 0) ? 0 : ((t - 2 > 12) ? 12 : t - 2);
            const int c2 = (t - 1 < 0) ? 0 : ((t - 1 > 12) ? 12 : t - 1);
            m[t] = fmaxf(s[c0], fmaxf(s[c1], s[c2]));
        }
        __half2* q = B + nd * BW + x * WX + y * WY;
        #pragma unroll
        for (int zp = 0; zp < 8; ++zp)
            q[zp] = __floats2half2_rn(m[2 * zp], m[2 * zp + 1]);
        q[8] = __floats2half2_rn(m[16], 0.0f);
    }
    __syncthreads();
}

__device__ __forceinline__ void max_y2(__half2* B) {
    for (int line = threadIdx.x; line < 2 * 19 * 9; line += blockDim.x) {
        int l = line, nd = 0;
        if (l >= 19 * 9) { l -= 19 * 9; nd = 1; }
        int zp = l % 9;
        int x  = l / 9;
        __half2* p = B + nd * BW + x * WX + zp;
        __half2 v0 = p[0], v1 = p[WY];
        #pragma unroll
        for (int t = 0; t < 17; ++t) {
            __half2 v2 = p[(t + 2) * WY];
            p[t * WY] = __hmax2(v0, __hmax2(v1, v2));
            v0 = v1; v1 = v2;
        }
    }
    __syncthreads();
}

__device__ __forceinline__ void max_x2(__half2* B) {
    for (int line = threadIdx.x; line < 2 * 17 * 9; line += blockDim.x) {
        int l = line, nd = 0;
        if (l >= 17 * 9) { l -= 17 * 9; nd = 1; }
        int zp = l % 9;
        int y  = l / 9;
        __half2* p = B + nd * BW + y * WY + zp;
        __half2 v0 = p[0], v1 = p[WX];
        #pragma unroll
        for (int t = 0; t < 17; ++t) {
            __half2 v2 = p[(t + 2) * WX];
            p[t * WX] = __hmax2(v0, __hmax2(v1, v2));
            v0 = v1; v1 = v2;
        }
    }
    __syncthreads();
}

__device__ __forceinline__ void avg5_z2(__half2* B) {
    const float inv9 = 1.0f / 9.0f;
    for (int line = threadIdx.x; line < 2 * 17 * 17; line += blockDim.x) {
        int l = line, nd = 0;
        if (l >= 17 * 17) { l -= 17 * 17; nd = 1; }
        int y = l % 17;
        int x = l / 17;
        __half2* p = B + nd * BW + x * WX + y * WY;
        float s[18];
        #pragma unroll
        for (int zp = 0; zp < 9; ++zp) {
            float2 f = __half22float2(p[zp]);
            s[2 * zp] = f.x; s[2 * zp + 1] = f.y;
        }
        float o[13];
        #pragma unroll
        for (int t = 0; t < 13; ++t)
            o[t] = ((s[t] + s[t + 4]) + 2.0f * (s[t + 1] + s[t + 3])
                    + 3.0f * s[t + 2]) * inv9;
        #pragma unroll
        for (int zp = 0; zp < 6; ++zp)
            p[zp] = __floats2half2_rn(o[2 * zp], o[2 * zp + 1]);
        p[6] = __floats2half2_rn(o[12], 0.0f);
    }
    __syncthreads();
}

__device__ __forceinline__ void avg5_y2(__half2* B) {
    const float inv9 = 1.0f / 9.0f;
    for (int line = threadIdx.x; line < 2 * 17 * 7; line += blockDim.x) {
        int l = line, nd = 0;
        if (l >= 17 * 7) { l -= 17 * 7; nd = 1; }
        int zp = l % 7;
        int x  = l / 7;
        __half2* p = B + nd * BW + x * WX + zp;
        float2 v0 = __half22float2(p[0]);
        float2 v1 = __half22float2(p[WY]);
        float2 v2 = __half22float2(p[2 * WY]);
        float2 v3 = __half22float2(p[3 * WY]);
        #pragma unroll
        for (int t = 0; t < 13; ++t) {
            float2 v4 = __half22float2(p[(t + 4) * WY]);
            float rx = ((v0.x + v4.x) + 2.0f * (v1.x + v3.x) + 3.0f * v2.x) * inv9;
            float ry = ((v0.y + v4.y) + 2.0f * (v1.y + v3.y) + 3.0f * v2.y) * inv9;
            p[t * WY] = __floats2half2_rn(rx, ry);
            v0 = v1; v1 = v2; v2 = v3; v3 = v4;
        }
    }
    __syncthreads();
}

// final fused avg-avg along x -> 13^3 fp16 to global (per node).
__device__ __forceinline__ void avg5_x_final2(const __half2* __restrict__ B,
                                              __half* __restrict__ gdst) {
    const float inv9 = 1.0f / 9.0f;
    for (int line = threadIdx.x; line < 2 * 13 * 7; line += blockDim.x) {
        int l = line, nd = 0;
        if (l >= 13 * 7) { l -= 13 * 7; nd = 1; }
        int zp = l % 7;
        int y  = l / 7;
        const __half2* p = B + nd * BW + y * WY + zp;
        __half* q = gdst + (size_t)nd * VOLP + y * LD + 2 * zp;
        float2 v0 = __half22float2(p[0]);
        float2 v1 = __half22float2(p[WX]);
        float2 v2 = __half22float2(p[2 * WX]);
        float2 v3 = __half22float2(p[3 * WX]);
        #pragma unroll
        for (int t = 0; t < 13; ++t) {
            float2 v4 = __half22float2(p[(t + 4) * WX]);
            float rx = ((v0.x + v4.x) + 2.0f * (v1.x + v3.x) + 3.0f * v2.x) * inv9;
            float ry = ((v0.y + v4.y) + 2.0f * (v1.y + v3.y) + 3.0f * v2.y) * inv9;
            q[t * 169] = __float2half_rn(rx);
            if (zp < 6) q[t * 169 + 1] = __float2half_rn(ry);
            v0 = v1; v1 = v2; v2 = v3; v3 = v4;
        }
    }
}

__device__ __forceinline__ void smooth2(const float* C, __half2* B,
                                        __half* __restrict__ gdst) {
    padmax_z2(C, B);
    max_y2(B);
    max_x2(B);
    avg5_z2(B);
    avg5_y2(B);
    avg5_x_final2(B, gdst);
}

// unpack 8 halves (one uint4) to fp32
__device__ __forceinline__ void h8(const uint4 u, float* f) {
    float2 a = __half22float2(*(const __half2*)&u.x);
    float2 b = __half22float2(*(const __half2*)&u.y);
    float2 c = __half22float2(*(const __half2*)&u.z);
    float2 d = __half22float2(*(const __half2*)&u.w);
    f[0] = a.x; f[1] = a.y; f[2] = b.x; f[3] = b.y;
    f[4] = c.x; f[5] = c.y; f[6] = d.x; f[7] = d.y;
}

// Kernel 1: two nodes per CTA. s1[n] = smooth(alpha1 + alpha0 * cost[n])
__global__ void __launch_bounds__(384)
k_stage1(const float* __restrict__ cost, const float* __restrict__ alpha) {
    extern __shared__ float sm[];
    float*   C = sm;                        // 2 * C_STR floats
    __half2* B = (__half2*)(sm + 2 * C_STR);
    int n0 = blockIdx.x * 2;
    float a0 = alpha[0], a1 = alpha[1];
    const float* src = cost + (size_t)n0 * VOL;
    for (int v = threadIdx.x; v < VOL; v += blockDim.x) {
        C[v]         = a1 + a0 * src[v];
        C[C_STR + v] = a1 + a0 * src[VOL + v];
    }
    __syncthreads();
    smooth2(C, B, g_s1 + (size_t)n0 * VOLP);
}

// Kernel 2: two nodes per CTA. gather s1 -> combine -> smooth -> s2
__global__ void __launch_bounds__(384)
k_stage2(const float* __restrict__ cost, const int* __restrict__ knn,
         const float* __restrict__ dist, const float* __restrict__ alpha) {
    extern __shared__ float sm[];
    float*   C = sm;
    __half2* B = (__half2*)(sm + 2 * C_STR);
    __shared__ float ws[2 * KNB];
    __shared__ int   nb[2 * KNB];
    int n0 = blockIdx.x * 2;
    if (threadIdx.x < 2 * KNB) {
        ws[threadIdx.x] = __expf(-dist[n0 * KNB + threadIdx.x] * 0.005f);
        nb[threadIdx.x] = knn[n0 * KNB + threadIdx.x];
    }
    __syncthreads();
    float a0 = alpha[0], a1 = alpha[1], a2 = alpha[2], a3 = alpha[3], a4 = alpha[4];
    float k1 = a2 * a0, k2 = a2 * a1 + a4;
    #pragma unroll
    for (int nd = 0; nd < 2; ++nd) {
        float w[KNB];
        float norm = 0.0f;
        #pragma unroll
        for (int k = 0; k < KNB; ++k) { w[k] = ws[nd * KNB + k]; norm += w[k]; }
        float k3 = a3 / norm;
        const uint4* p[KNB];
        #pragma unroll
        for (int k = 0; k < KNB; ++k)
            p[k] = (const uint4*)(g_s1 + (size_t)nb[nd * KNB + k] * VOLP);
        const float* src = cost + (size_t)(n0 + nd) * VOL;
        float* Cn = C + nd * C_STR;
        for (int v = threadIdx.x; v < VOLP / 8; v += blockDim.x) {  // 276, 1 sweep
            float acc[8] = {0, 0, 0, 0, 0, 0, 0, 0};
            #pragma unroll
            for (int k = 0; k < KNB; ++k) {
                float f[8];
                h8(p[k][v], f);
                #pragma unroll
                for (int j = 0; j < 8; ++j) acc[j] += w[k] * f[j];
            }
            int base = 8 * v;
            float r[8];
            #pragma unroll
            for (int j = 0; j < 8; ++j) {
                float cs = (base + j < VOL) ? src[base + j] : 0.0f;
                r[j] = k2 + k1 * cs + k3 * acc[j];
            }
            float4* Cv = (float4*)(Cn + base);
            Cv[0] = make_float4(r[0], r[1], r[2], r[3]);
            Cv[1] = make_float4(r[4], r[5], r[6], r[7]);
        }
    }
    __syncthreads();
    smooth2(C, B, g_s2 + (size_t)n0 * VOLP);
}

// Kernel 3: single sweep, 288 threads: 274 uint4 vectors + 5-element tail.
__global__ void __launch_bounds__(288)
k_stage3(const int* __restrict__ knn, const float* __restrict__ dist,
         const float* __restrict__ alpha, float* __restrict__ out) {
    __shared__ float ws[KNB];
    __shared__ int   nb[KNB];
    int n = blockIdx.x;
    if (threadIdx.x < KNB) {
        ws[threadIdx.x] = __expf(-dist[n * KNB + threadIdx.x] * 0.005f);
        nb[threadIdx.x] = knn[n * KNB + threadIdx.x];
    }
    __syncthreads();
    float w[KNB];
    float norm = 0.0f;
    #pragma unroll
    for (int k = 0; k < KNB; ++k) { w[k] = ws[k]; norm += w[k]; }
    float s = alpha[5] / norm;
    float* dst = out + (size_t)n * VOL;
    int v = threadIdx.x;
    if (v < VOL / 8) {                       // 274 full uint4 groups
        float acc[8] = {0, 0, 0, 0, 0, 0, 0, 0};
        #pragma unroll
        for (int k = 0; k < KNB; ++k) {
            const uint4* p = (const uint4*)(g_s2 + (size_t)nb[k] * VOLP);
            float f[8];
            h8(p[v], f);
            #pragma unroll
            for (int j = 0; j < 8; ++j) acc[j] += w[k] * f[j];
        }
        float* q = dst + 8 * v;
        #pragma unroll
        for (int j = 0; j < 8; ++j) q[j] = s * acc[j];
    } else if (v < VOL / 8 + (VOL - (VOL / 8) * 8)) {   // tail 2192..2196
        int idx = (VOL / 8) * 8 + (v - VOL / 8);
        float acc = 0.0f;
        #pragma unroll
        for (int k = 0; k < KNB; ++k)
            acc += w[k] * __half2float(g_s2[(size_t)nb[k] * VOLP + idx]);
        dst[idx] = s * acc;
    }
}

extern "C" void kernel_launch(void* const* d_in, const int* in_sizes, int n_in,
                              void* d_out, int out_size) {
    const float* cost  = (const float*)d_in[0];
    const int*   knn   = (const int*)d_in[1];
    const float* dist  = (const float*)d_in[2];
    const float* alpha = (const float*)d_in[3];
    float* out = (float*)d_out;

    k_stage1<<<NN / 2, 384, SMEMB>>>(cost, alpha);
    k_stage2<<<NN / 2, 384, SMEMB>>>(cost, knn, dist, alpha);
    k_stage3<<<NN, 288>>>(knn, dist, alpha, out);
}